// round 2
// baseline (speedup 1.0000x reference)
#include <cuda_runtime.h>
#include <math.h>

#define MAXSPAN 66
#define NTHREADS 256

struct Params {
    const float* feat[4];
    int H[4];
    int W[4];
    float scale[4];
    int C;
};

// Replicates reference `prep` + dense separable-weight accumulation for one axis.
// c1,c2: scaled box coords; L: axis length. Writes dense weights w[0..n),
// covering feature indices [o0, o0+n).
__device__ __forceinline__ void build_axis(float c1, float c2, int L,
                                           float* w, int* p_o0, int* p_n) {
    float sz  = fmaxf(__fadd_rn(c2, -c1), 1.0f);
    float bin = __fdiv_rn(sz, 14.0f);
    int   lo_a[28], hi_a[28];
    float fr_a[28];
    bool  va[28];
    int mn = 0x7fffffff, mx = -1;
#pragma unroll
    for (int s = 0; s < 28; s++) {
        // offs = s//2 + (s%2 + 0.5)/2  (exact in fp32)
        float off = (float)(s >> 1) + ((float)(s & 1) + 0.5f) * 0.5f;
        float v   = __fadd_rn(c1, __fmul_rn(off, bin));
        bool valid = (v >= -1.0f) && (v <= (float)L);
        v = fmaxf(v, 0.0f);
        int lo = (int)v;   // floor, v >= 0
        int hi;
        float fr;
        if (lo >= L - 1) { lo = L - 1; hi = L - 1; fr = 0.0f; }
        else             { hi = lo + 1; fr = v - (float)lo; }
        lo_a[s] = lo; hi_a[s] = hi; fr_a[s] = fr; va[s] = valid;
        if (valid) { mn = min(mn, lo); mx = max(mx, hi); }
    }
    if (mx < 0) { *p_o0 = 0; *p_n = 0; return; }   // all samples invalid
    int n = mx - mn + 1;
    if (n > MAXSPAN) n = MAXSPAN;                   // safety clamp (never hit)
    for (int i = 0; i < n; i++) w[i] = 0.0f;
#pragma unroll
    for (int s = 0; s < 28; s++) {
        if (!va[s]) continue;
        int l = lo_a[s] - mn, h = hi_a[s] - mn;
        if (l < n) w[l] += 1.0f - fr_a[s];
        if (h < n) w[h] += fr_a[s];
    }
    *p_o0 = mn; *p_n = n;
}

__global__ __launch_bounds__(NTHREADS)
void roi_align_mean_kernel(Params p, const float* __restrict__ boxes,
                           const int* __restrict__ bids,
                           float* __restrict__ out) {
    const int r   = blockIdx.x;
    const int lvl = blockIdx.y;
    const int H = p.H[lvl], W = p.W[lvl];
    const float scale = p.scale[lvl];

    __shared__ float  s_wy[MAXSPAN], s_wx[MAXSPAN];
    __shared__ int    s_y0, s_x0, s_ny, s_nx;
    __shared__ float2 s_wo[MAXSPAN * MAXSPAN];   // (wy*wx, pixel offset)

    const int tid = threadIdx.x;

    if (tid == 0) {
        float y1 = __fmul_rn(boxes[r * 4 + 1], scale);
        float y2 = __fmul_rn(boxes[r * 4 + 3], scale);
        build_axis(y1, y2, H, s_wy, &s_y0, &s_ny);
    } else if (tid == 32) {
        float x1 = __fmul_rn(boxes[r * 4 + 0], scale);
        float x2 = __fmul_rn(boxes[r * 4 + 2], scale);
        build_axis(x1, x2, W, s_wx, &s_x0, &s_nx);
    }
    __syncthreads();

    const int ny = s_ny, nx = s_nx, y0 = s_y0, x0 = s_x0;
    const int total = ny * nx;

    // Build flattened (weight, offset) table cooperatively.
    for (int i = tid; i < total; i += NTHREADS) {
        int yy = i / nx;
        int xx = i - yy * nx;
        float wv = s_wy[yy] * s_wx[xx];
        int off  = (y0 + yy) * W + (x0 + xx);
        s_wo[i]  = make_float2(wv, __int_as_float(off));
    }
    __syncthreads();

    const int C = p.C;
    const int b = bids[r];
    const float* fb = p.feat[lvl] + (size_t)b * C * H * W;
    const int warp = tid >> 5, lane = tid & 31;
    const int outbase = r * 4 * C + lvl * C;

    for (int c = warp; c < C; c += NTHREADS / 32) {
        const float* fc = fb + (size_t)c * H * W;
        float acc = 0.0f;
#pragma unroll 4
        for (int i = lane; i < total; i += 32) {
            float2 wo = s_wo[i];
            acc = fmaf(wo.x, __ldg(fc + __float_as_int(wo.y)), acc);
        }
#pragma unroll
        for (int o = 16; o; o >>= 1)
            acc += __shfl_xor_sync(0xffffffffu, acc, o);
        if (lane == 0) out[outbase + c] = acc * (1.0f / 784.0f);
    }
}

extern "C" void kernel_launch(void* const* d_in, const int* in_sizes, int n_in,
                              void* d_out, int out_size) {
    const int B = 2, C = 256;
    Params p;
    for (int i = 0; i < 4; i++) {
        p.feat[i] = (const float*)d_in[i];
        long npix = (long)in_sizes[i] / ((long)B * C);
        // image aspect 800:1280 = 5:8 -> H = sqrt(npix * 5/8)
        int Hh = (int)(sqrt((double)npix * 5.0 / 8.0) + 0.5);
        int Ww = (int)(npix / Hh);
        p.H[i] = Hh;
        p.W[i] = Ww;
        p.scale[i] = 0.25f / (float)(1 << i);
    }
    p.C = C;
    const int R = in_sizes[4] / 4;
    const float* boxes = (const float*)d_in[4];
    const int*   bids  = (const int*)d_in[5];

    dim3 grid(R, 4);
    roi_align_mean_kernel<<<grid, NTHREADS>>>(p, boxes, bids, (float*)d_out);
}

// round 3
// speedup vs baseline: 1.0210x; 1.0210x over previous
#include <cuda_runtime.h>
#include <math.h>

#define MAXSPAN 66
#define WSTRIDE 72
#define NRL     1024          // R(256) * 4 levels

struct Params {
    const float* feat[4];
    int H[4];
    int W[4];
    float scale[4];
    int C;
};

// Scratch (allocation-free rule: __device__ globals)
__device__ float              g_wy[NRL * WSTRIDE];
__device__ float              g_wx[NRL * WSTRIDE];
__device__ int4               g_meta[NRL];     // {ny, nx, base_off(y0*W+x0), 0}
__device__ unsigned long long g_magic[NRL];    // ceil(2^32/nx)

// Replicates reference `prep` + dense separable-weight accumulation for one axis.
// Writes dense weights (scaled by `wscale`) to w[0..n), covering [o0, o0+n).
__device__ void build_axis(float c1, float c2, int L, float wscale,
                           float* w, int* p_o0, int* p_n) {
    float sz  = fmaxf(__fadd_rn(c2, -c1), 1.0f);
    float bin = __fdiv_rn(sz, 14.0f);
    int   lo_a[28], hi_a[28];
    float fr_a[28];
    bool  va[28];
    int mn = 0x7fffffff, mx = -1;
#pragma unroll
    for (int s = 0; s < 28; s++) {
        float off = (float)(s >> 1) + ((float)(s & 1) + 0.5f) * 0.5f;
        float v   = __fadd_rn(c1, __fmul_rn(off, bin));
        bool valid = (v >= -1.0f) && (v <= (float)L);
        v = fmaxf(v, 0.0f);
        int lo = (int)v;   // floor, v >= 0
        int hi;
        float fr;
        if (lo >= L - 1) { lo = L - 1; hi = L - 1; fr = 0.0f; }
        else             { hi = lo + 1; fr = v - (float)lo; }
        lo_a[s] = lo; hi_a[s] = hi; fr_a[s] = fr; va[s] = valid;
        if (valid) { mn = min(mn, lo); mx = max(mx, hi); }
    }
    if (mx < 0) { *p_o0 = 0; *p_n = 0; return; }   // all samples invalid
    int n = mx - mn + 1;
    if (n > MAXSPAN) n = MAXSPAN;
    for (int i = 0; i < n; i++) w[i] = 0.0f;
#pragma unroll
    for (int s = 0; s < 28; s++) {
        if (!va[s]) continue;
        int l = lo_a[s] - mn, h = hi_a[s] - mn;
        if (l < n) w[l] += 1.0f - fr_a[s];
        if (h < n) w[h] += fr_a[s];
    }
    for (int i = 0; i < n; i++) w[i] *= wscale;
    *p_o0 = mn; *p_n = n;
}

// One block per (roi, level). Two warps: warp0 builds Y weights, warp1 builds X.
__global__ void prep_kernel(Params p, const float* __restrict__ boxes) {
    const int r   = blockIdx.x;
    const int lvl = blockIdx.y;
    const int rl  = r * 4 + lvl;
    __shared__ int sh_o0[2], sh_n[2];

    if (threadIdx.x == 0) {
        float y1 = __fmul_rn(boxes[r * 4 + 1], p.scale[lvl]);
        float y2 = __fmul_rn(boxes[r * 4 + 3], p.scale[lvl]);
        int o0, n;
        build_axis(y1, y2, p.H[lvl], 1.0f / 28.0f, &g_wy[rl * WSTRIDE], &o0, &n);
        sh_o0[0] = o0; sh_n[0] = n;
    } else if (threadIdx.x == 32) {
        float x1 = __fmul_rn(boxes[r * 4 + 0], p.scale[lvl]);
        float x2 = __fmul_rn(boxes[r * 4 + 2], p.scale[lvl]);
        int o0, n;
        build_axis(x1, x2, p.W[lvl], 1.0f / 28.0f, &g_wx[rl * WSTRIDE], &o0, &n);
        sh_o0[1] = o0; sh_n[1] = n;
    }
    __syncthreads();
    if (threadIdx.x == 0) {
        int ny = sh_n[0], nx = sh_n[1];
        int base = sh_o0[0] * p.W[lvl] + sh_o0[1];
        g_meta[rl] = make_int4(ny, nx, base, 0);
        int d = nx > 0 ? nx : 1;
        g_magic[rl] = (0x100000000ULL + (unsigned long long)d - 1) /
                      (unsigned long long)d;
    }
}

// grid (R*4, C/64). Block = 128 threads = 4 warps; each warp does 16 channels
// in 4 passes of 4 (4 independent accumulators per pass for MLP).
__global__ __launch_bounds__(128, 10)
void roi_main_kernel(Params p, const int* __restrict__ bids,
                     float* __restrict__ out) {
    const int rl  = blockIdx.x;
    const int lvl = rl & 3;
    const int r   = rl >> 2;
    const int W   = p.W[lvl];
    const int HW  = p.H[lvl] * W;
    const int C   = p.C;

    __shared__ float s_wy[MAXSPAN], s_wx[MAXSPAN];

    const int4 m = g_meta[rl];
    const int ny = m.x, nx = m.y;
    const unsigned long long magic = g_magic[rl];

    const int tid = threadIdx.x;
    for (int i = tid; i < ny; i += 128) s_wy[i] = g_wy[rl * WSTRIDE + i];
    for (int i = tid; i < nx; i += 128) s_wx[i] = g_wx[rl * WSTRIDE + i];
    __syncthreads();

    const int total = ny * nx;
    const int b = __ldg(&bids[r]);
    const float* __restrict__ fb = p.feat[lvl] + (size_t)b * C * HW + m.z;

    const int warp = tid >> 5, lane = tid & 31;
    const int cbase = blockIdx.y * 64 + warp * 16;
    const int outbase = r * 4 * C + lvl * C;

#pragma unroll
    for (int k = 0; k < 4; k++) {
        const int c = cbase + k * 4;
        const float* __restrict__ f0 = fb + (size_t)c * HW;
        const float* __restrict__ f1 = f0 + HW;
        const float* __restrict__ f2 = f1 + HW;
        const float* __restrict__ f3 = f2 + HW;
        float a0 = 0.f, a1 = 0.f, a2 = 0.f, a3 = 0.f;
#pragma unroll 2
        for (int i = lane; i < total; i += 32) {
            unsigned yy = (unsigned)(((unsigned long long)(unsigned)i * magic) >> 32);
            unsigned xx = (unsigned)i - yy * (unsigned)nx;
            float wv = s_wy[yy] * s_wx[xx];
            int off = (int)(yy * (unsigned)W + xx);
            a0 = fmaf(wv, __ldg(f0 + off), a0);
            a1 = fmaf(wv, __ldg(f1 + off), a1);
            a2 = fmaf(wv, __ldg(f2 + off), a2);
            a3 = fmaf(wv, __ldg(f3 + off), a3);
        }
#pragma unroll
        for (int o = 16; o; o >>= 1) {
            a0 += __shfl_xor_sync(0xffffffffu, a0, o);
            a1 += __shfl_xor_sync(0xffffffffu, a1, o);
            a2 += __shfl_xor_sync(0xffffffffu, a2, o);
            a3 += __shfl_xor_sync(0xffffffffu, a3, o);
        }
        if (lane == 0) {
            out[outbase + c + 0] = a0;
            out[outbase + c + 1] = a1;
            out[outbase + c + 2] = a2;
            out[outbase + c + 3] = a3;
        }
    }
}

extern "C" void kernel_launch(void* const* d_in, const int* in_sizes, int n_in,
                              void* d_out, int out_size) {
    const int B = 2, C = 256;
    Params p;
    for (int i = 0; i < 4; i++) {
        p.feat[i] = (const float*)d_in[i];
        long npix = (long)in_sizes[i] / ((long)B * C);
        int Hh = (int)(sqrt((double)npix * 5.0 / 8.0) + 0.5);  // 800:1280 aspect
        int Ww = (int)(npix / Hh);
        p.H[i] = Hh;
        p.W[i] = Ww;
        p.scale[i] = 0.25f / (float)(1 << i);
    }
    p.C = C;
    const int R = in_sizes[4] / 4;
    const float* boxes = (const float*)d_in[4];
    const int*   bids  = (const int*)d_in[5];

    prep_kernel<<<dim3(R, 4), 64>>>(p, boxes);
    roi_main_kernel<<<dim3(R * 4, C / 64), 128>>>(p, bids, (float*)d_out);
}

// round 5
// speedup vs baseline: 4.5281x; 4.4351x over previous
#include <cuda_runtime.h>
#include <math.h>

#define MAXSPAN 66
#define WSTRIDE 72            // padded x-weight stride (shift<=3 + 66 -> <=72)
#define NRL     1024          // R(256) * 4 levels

struct Params {
    const float* feat[4];
    int H[4];
    int W[4];
    float scale[4];
    int C;
};

// Scratch (allocation-free rule: __device__ globals)
__device__ float              g_wy[NRL * WSTRIDE];
__device__ float              g_wx[NRL * WSTRIDE];   // zero-padded, 4-aligned window
__device__ int4               g_meta[NRL];           // {ny, nx4, base_off, 0}
__device__ unsigned long long g_magic[NRL];          // ceil(2^32/nx4), 64-bit!

// Replicates reference `prep` + dense separable-weight accumulation.
__device__ void build_axis(float c1, float c2, int L, float wscale,
                           float* w, int* p_o0, int* p_n) {
    float sz  = fmaxf(__fadd_rn(c2, -c1), 1.0f);
    float bin = __fdiv_rn(sz, 14.0f);
    int   lo_a[28], hi_a[28];
    float fr_a[28];
    bool  va[28];
    int mn = 0x7fffffff, mx = -1;
#pragma unroll
    for (int s = 0; s < 28; s++) {
        float off = (float)(s >> 1) + ((float)(s & 1) + 0.5f) * 0.5f;
        float v   = __fadd_rn(c1, __fmul_rn(off, bin));
        bool valid = (v >= -1.0f) && (v <= (float)L);
        v = fmaxf(v, 0.0f);
        int lo = (int)v;   // floor, v >= 0
        int hi;
        float fr;
        if (lo >= L - 1) { lo = L - 1; hi = L - 1; fr = 0.0f; }
        else             { hi = lo + 1; fr = v - (float)lo; }
        lo_a[s] = lo; hi_a[s] = hi; fr_a[s] = fr; va[s] = valid;
        if (valid) { mn = min(mn, lo); mx = max(mx, hi); }
    }
    if (mx < 0) { *p_o0 = 0; *p_n = 0; return; }
    int n = mx - mn + 1;
    if (n > MAXSPAN) n = MAXSPAN;
    for (int i = 0; i < n; i++) w[i] = 0.0f;
#pragma unroll
    for (int s = 0; s < 28; s++) {
        if (!va[s]) continue;
        int l = lo_a[s] - mn, h = hi_a[s] - mn;
        if (l < n) w[l] += 1.0f - fr_a[s];
        if (h < n) w[h] += fr_a[s];
    }
    for (int i = 0; i < n; i++) w[i] *= wscale;
    *p_o0 = mn; *p_n = n;
}

__global__ void prep_kernel(Params p, const float* __restrict__ boxes) {
    const int r   = blockIdx.x;
    const int lvl = blockIdx.y;
    const int rl  = r * 4 + lvl;
    __shared__ int sh_ny, sh_y0, sh_nx4, sh_x0al;

    if (threadIdx.x == 0) {
        float y1 = __fmul_rn(boxes[r * 4 + 1], p.scale[lvl]);
        float y2 = __fmul_rn(boxes[r * 4 + 3], p.scale[lvl]);
        int o0, n;
        build_axis(y1, y2, p.H[lvl], 1.0f / 28.0f, &g_wy[rl * WSTRIDE], &o0, &n);
        sh_y0 = o0; sh_ny = n;
    } else if (threadIdx.x == 32) {
        float wtmp[MAXSPAN];
        float x1 = __fmul_rn(boxes[r * 4 + 0], p.scale[lvl]);
        float x2 = __fmul_rn(boxes[r * 4 + 2], p.scale[lvl]);
        int o0, n;
        build_axis(x1, x2, p.W[lvl], 1.0f / 28.0f, wtmp, &o0, &n);
        int x0al  = o0 & ~3;
        int shift = o0 - x0al;
        int nxp   = (shift + n + 3) & ~3;          // padded width (mult of 4)
        float* dst = &g_wx[rl * WSTRIDE];
        for (int j = 0; j < nxp; j++) {
            int k = j - shift;
            dst[j] = (k >= 0 && k < n) ? wtmp[k] : 0.0f;
        }
        sh_x0al = x0al; sh_nx4 = nxp >> 2;
    }
    __syncthreads();
    if (threadIdx.x == 0) {
        int ny  = sh_ny;
        int nx4 = sh_nx4;
        int base = sh_y0 * p.W[lvl] + sh_x0al;
        g_meta[rl] = make_int4(ny, nx4, base, 0);
        int d = nx4 > 0 ? nx4 : 1;
        g_magic[rl] = (0x100000000ULL + (unsigned long long)d - 1) /
                      (unsigned long long)d;        // exact for d=1 as 64-bit
    }
}

// grid (R*4, 8). 128 threads = 4 warps; channel group = 32 channels;
// each warp: 8 channels in 2 passes of 4, float4 loads per pixel-quad.
__global__ __launch_bounds__(128, 8)
void roi_main_kernel(Params p, const int* __restrict__ bids,
                     float* __restrict__ out) {
    const int rl  = blockIdx.x;
    const int lvl = rl & 3;
    const int r   = rl >> 2;
    const int W   = p.W[lvl];
    const int HW  = p.H[lvl] * W;
    const int C   = p.C;

    __shared__ float  s_wy[MAXSPAN];
    __shared__ float4 s_wx4[WSTRIDE / 4];

    const int4 m = g_meta[rl];
    const int ny = m.x, nx4 = m.y;
    const unsigned long long magic = g_magic[rl];

    const int tid = threadIdx.x;
    for (int i = tid; i < ny; i += 128) s_wy[i] = g_wy[rl * WSTRIDE + i];
    for (int i = tid; i < nx4; i += 128)
        s_wx4[i] = ((const float4*)&g_wx[rl * WSTRIDE])[i];
    __syncthreads();

    const int total = ny * nx4;
    const int b = __ldg(&bids[r]);
    const float* __restrict__ fb = p.feat[lvl] + (size_t)b * C * HW + m.z;

    const int warp = tid >> 5, lane = tid & 31;
    const int cbase = blockIdx.y * 32 + warp * 8;
    const int outbase = r * 4 * C + lvl * C;

#pragma unroll
    for (int k = 0; k < 2; k++) {
        const int c = cbase + k * 4;
        const float4* __restrict__ f0 = (const float4*)(fb + (size_t)c * HW);
        const float4* __restrict__ f1 = (const float4*)(fb + (size_t)(c + 1) * HW);
        const float4* __restrict__ f2 = (const float4*)(fb + (size_t)(c + 2) * HW);
        const float4* __restrict__ f3 = (const float4*)(fb + (size_t)(c + 3) * HW);
        float a0 = 0.f, a1 = 0.f, a2 = 0.f, a3 = 0.f;
        for (int i = lane; i < total; i += 32) {
            unsigned yy  = (unsigned)(((unsigned long long)(unsigned)i * magic) >> 32);
            unsigned xx4 = (unsigned)i - yy * (unsigned)nx4;
            int off = (int)(yy * (unsigned)(W >> 2) + xx4);
            float  wy = s_wy[yy];
            float4 wx = s_wx4[xx4];
            float4 w4 = make_float4(wy * wx.x, wy * wx.y, wy * wx.z, wy * wx.w);
            float4 v0 = __ldg(f0 + off);
            float4 v1 = __ldg(f1 + off);
            float4 v2 = __ldg(f2 + off);
            float4 v3 = __ldg(f3 + off);
            a0 = fmaf(w4.x, v0.x, fmaf(w4.y, v0.y, fmaf(w4.z, v0.z, fmaf(w4.w, v0.w, a0))));
            a1 = fmaf(w4.x, v1.x, fmaf(w4.y, v1.y, fmaf(w4.z, v1.z, fmaf(w4.w, v1.w, a1))));
            a2 = fmaf(w4.x, v2.x, fmaf(w4.y, v2.y, fmaf(w4.z, v2.z, fmaf(w4.w, v2.w, a2))));
            a3 = fmaf(w4.x, v3.x, fmaf(w4.y, v3.y, fmaf(w4.z, v3.z, fmaf(w4.w, v3.w, a3))));
        }
#pragma unroll
        for (int o = 16; o; o >>= 1) {
            a0 += __shfl_xor_sync(0xffffffffu, a0, o);
            a1 += __shfl_xor_sync(0xffffffffu, a1, o);
            a2 += __shfl_xor_sync(0xffffffffu, a2, o);
            a3 += __shfl_xor_sync(0xffffffffu, a3, o);
        }
        if (lane == 0) {
            out[outbase + c + 0] = a0;
            out[outbase + c + 1] = a1;
            out[outbase + c + 2] = a2;
            out[outbase + c + 3] = a3;
        }
    }
}

extern "C" void kernel_launch(void* const* d_in, const int* in_sizes, int n_in,
                              void* d_out, int out_size) {
    const int B = 2, C = 256;
    Params p;
    for (int i = 0; i < 4; i++) {
        p.feat[i] = (const float*)d_in[i];
        long npix = (long)in_sizes[i] / ((long)B * C);
        int Hh = (int)(sqrt((double)npix * 5.0 / 8.0) + 0.5);  // 800:1280 aspect
        int Ww = (int)(npix / Hh);
        p.H[i] = Hh;
        p.W[i] = Ww;
        p.scale[i] = 0.25f / (float)(1 << i);
    }
    p.C = C;
    const int R = in_sizes[4] / 4;
    const float* boxes = (const float*)d_in[4];
    const int*   bids  = (const int*)d_in[5];

    prep_kernel<<<dim3(R, 4), 64>>>(p, boxes);
    roi_main_kernel<<<dim3(R * 4, 8), 128>>>(p, bids, (float*)d_out);
}